// round 16
// baseline (speedup 1.0000x reference)
#include <cuda_runtime.h>
#include <cuda_bf16.h>
#include <math.h>
#include <stdint.h>

// Problem constants
#define BB 4
#define TT 4096
#define DD 1024
#define HH 16
#define HD 64
#define TS 1024
#define MROWS (BB*TS)
#define BH (BB*HH)

// Scratch (allocation-free: __device__ globals)
__device__ float g_qkv[MROWS*3*DD];                          // 48 MB qkv fp32
__device__ float g_proj[MROWS*DD];                           // 16 MB out projection
__device__ __nv_bfloat16 g_a1h[MROWS*DD], g_a1l[MROWS*DD];   // LN rows, split bf16
__device__ __nv_bfloat16 g_a2h[MROWS*DD], g_a2l[MROWS*DD];   // attn out, split bf16
__device__ __nv_bfloat16 g_wqh[3*DD*DD], g_wql[3*DD*DD];     // W_qkv^T split
__device__ __nv_bfloat16 g_woh[DD*DD],  g_wol[DD*DD];        // W_out^T split
// RoPE'd split-bf16 attention operands, [B,H,Ts,64]
__device__ __nv_bfloat16 g_qh[BH*TS*HD], g_ql[BH*TS*HD];
__device__ __nv_bfloat16 g_kh[BH*TS*HD], g_kl[BH*TS*HD];
__device__ __nv_bfloat16 g_vh[BH*TS*HD], g_vl[BH*TS*HD];

__device__ __forceinline__ uint32_t smem_u32(const void* p) {
    uint32_t a;
    asm("{ .reg .u64 t; cvta.to.shared.u64 t, %1; cvt.u32.u64 %0, t; }"
        : "=r"(a) : "l"(p));
    return a;
}
#define SWZ(x) ((x) ^ (((x) >> 3) & 0x70))

#define LDSM4(r, addr) \
    asm volatile("ldmatrix.sync.aligned.m8n8.x4.shared.b16 {%0,%1,%2,%3}, [%4];" \
        : "=r"((r)[0]), "=r"((r)[1]), "=r"((r)[2]), "=r"((r)[3]) : "r"(addr))

#define LDSM4T(r, addr) \
    asm volatile("ldmatrix.sync.aligned.m8n8.x4.trans.shared.b16 {%0,%1,%2,%3}, [%4];" \
        : "=r"((r)[0]), "=r"((r)[1]), "=r"((r)[2]), "=r"((r)[3]) : "r"(addr))

#define MMA16816(d, a, b) \
    asm volatile("mma.sync.aligned.m16n8k16.row.col.f32.bf16.bf16.f32 " \
        "{%0,%1,%2,%3},{%4,%5,%6,%7},{%8,%9},{%0,%1,%2,%3};" \
        : "+f"((d)[0]), "+f"((d)[1]), "+f"((d)[2]), "+f"((d)[3]) \
        : "r"((a)[0]), "r"((a)[1]), "r"((a)[2]), "r"((a)[3]), \
          "r"((b)[0]), "r"((b)[1]))

#define CPA16(dst, src) \
    asm volatile("cp.async.cg.shared.global [%0], [%1], 16;" :: "r"(dst), "l"(src) : "memory")
#define CPA_COMMIT() asm volatile("cp.async.commit_group;" ::: "memory")
#define CPA_WAIT0()  asm volatile("cp.async.wait_group 0;" ::: "memory")
#define CPA_WAIT1()  asm volatile("cp.async.wait_group 1;" ::: "memory")

#define GSMEM 99328      // gemm: 3 x 32KB stages + align slack (2 CTAs/SM)
#define ATT_SMEM 82944   // attn: 2 x 32KB (K/V hi/lo) + 16KB Q + slack

__device__ __forceinline__ void pack_split(float a, float b, uint32_t& hi, uint32_t& lo) {
    __nv_bfloat162 h = __floats2bfloat162_rn(a, b);
    float ra = a - __bfloat162float(h.x);
    float rb = b - __bfloat162float(h.y);
    __nv_bfloat162 l2 = __floats2bfloat162_rn(ra, rb);
    hi = *(uint32_t*)&h;
    lo = *(uint32_t*)&l2;
}

// ---------------------------------------------------------------------------
// LayerNorm on strided rows -> split-bf16 A1 (hi/lo)
// ---------------------------------------------------------------------------
__global__ __launch_bounds__(256) void ln_kernel(const float* __restrict__ x,
                                                 const float* __restrict__ w,
                                                 const float* __restrict__ bias)
{
    int row = blockIdx.x;
    int b = row >> 10, ts = row & 1023;
    int tid = threadIdx.x;
    const float4* xr = (const float4*)(x + ((size_t)(b*TT + ts*4))*DD);
    float4 v = xr[tid];
    float s  = v.x + v.y + v.z + v.w;
    float sq = v.x*v.x + v.y*v.y + v.z*v.z + v.w*v.w;
    #pragma unroll
    for (int o = 16; o > 0; o >>= 1) {
        s  += __shfl_xor_sync(0xffffffffu, s,  o);
        sq += __shfl_xor_sync(0xffffffffu, sq, o);
    }
    __shared__ float rs[8], rq[8];
    int wid = tid >> 5, lane = tid & 31;
    if (lane == 0) { rs[wid] = s; rq[wid] = sq; }
    __syncthreads();
    if (tid == 0) {
        float S = 0.f, Q = 0.f;
        #pragma unroll
        for (int i = 0; i < 8; i++) { S += rs[i]; Q += rq[i]; }
        rs[0] = S; rq[0] = Q;
    }
    __syncthreads();
    float mean = rs[0] * (1.0f/DD);
    float var  = rq[0] * (1.0f/DD) - mean*mean;
    float rstd = rsqrtf(var + 1e-5f);
    float4 wv = ((const float4*)w)[tid];
    float4 bv = ((const float4*)bias)[tid];
    float vals[4];
    vals[0] = (v.x - mean)*rstd*wv.x + bv.x;
    vals[1] = (v.y - mean)*rstd*wv.y + bv.y;
    vals[2] = (v.z - mean)*rstd*wv.z + bv.z;
    vals[3] = (v.w - mean)*rstd*wv.w + bv.w;
    size_t base = (size_t)row*DD + tid*4;
    #pragma unroll
    for (int j = 0; j < 4; j += 2) {
        uint32_t H, L;
        pack_split(vals[j], vals[j+1], H, L);
        *(uint32_t*)(g_a1h + base + j) = H;
        *(uint32_t*)(g_a1l + base + j) = L;
    }
}

// ---------------------------------------------------------------------------
// Weight transpose + split: W[K=1024][N] fp32 -> T[N][1024] bf16 hi/lo
// ---------------------------------------------------------------------------
__global__ __launch_bounds__(256) void wsplit(const float* __restrict__ W,
                                              __nv_bfloat16* __restrict__ Th,
                                              __nv_bfloat16* __restrict__ Tl,
                                              int N)
{
    __shared__ float t[32][33];
    int n0 = blockIdx.x*32, k0 = blockIdx.y*32;
    int tx = threadIdx.x & 31, ty = threadIdx.x >> 5;
    #pragma unroll
    for (int i = 0; i < 4; i++)
        t[ty + i*8][tx] = W[(size_t)(k0 + ty + i*8)*N + n0 + tx];
    __syncthreads();
    #pragma unroll
    for (int i = 0; i < 4; i++) {
        int n = n0 + ty + i*8, k = k0 + tx;
        float v = t[tx][ty + i*8];
        __nv_bfloat16 h = __float2bfloat16(v);
        __nv_bfloat16 l = __float2bfloat16(v - __bfloat162float(h));
        Th[(size_t)n*DD + k] = h;
        Tl[(size_t)n*DD + k] = l;
    }
}

// ---------------------------------------------------------------------------
// mma.sync split-bf16 GEMM v3: C = A @ B^T + bias.
// Tile 128x128, 8 warps (4m x 2n, 32x64 each), K-chunk 32,
// hi/lo packed in one 128B smem row ([64B hi | 64B lo]),
// 3-stage cp.async pipeline (32KB/stage), 2 CTAs per SM.
// ---------------------------------------------------------------------------
__global__ __launch_bounds__(256, 2)
void gemm_mma(const __nv_bfloat16* __restrict__ Ah, const __nv_bfloat16* __restrict__ Al,
              const __nv_bfloat16* __restrict__ Bh, const __nv_bfloat16* __restrict__ Bl,
              const float* __restrict__ bias, float* __restrict__ C, int ldc)
{
    extern __shared__ char dsm[];
    uint32_t sb = (smem_u32(dsm) + 1023) & ~1023u;
    int tid = threadIdx.x, lane = tid & 31, wid = tid >> 5;
    int bn = blockIdx.x*128, bm = blockIdx.y*128;
    int m0 = (wid & 3)*32, n0 = (wid >> 2)*64;

    // Copy mapping: row = tid/2; half 0 -> hi bytes [0,64), half 1 -> lo [64,128)
    int row = tid >> 1, half = tid & 1;
    const uint4* srcA = (const uint4*)((half ? Al : Ah) + (size_t)(bm+row)*DD);
    const uint4* srcB = (const uint4*)((half ? Bl : Bh) + (size_t)(bn+row)*DD);
    uint32_t so = (uint32_t)(row*128 + half*64);

    float acc[2][8][4];
    #pragma unroll
    for (int i = 0; i < 2; i++)
        #pragma unroll
        for (int j = 0; j < 8; j++)
            #pragma unroll
            for (int k = 0; k < 4; k++) acc[i][j][k] = 0.f;

    // chunk c covers K elems [c*32, c*32+32) = 4 uint4 per row per array
    auto copy_chunk = [&](int c, int buf) {
        uint32_t bbase = sb + buf*32768;
        const uint4* sa = srcA + c*4;
        const uint4* sbp = srcB + c*4;
        #pragma unroll
        for (int i = 0; i < 4; i++) {
            uint32_t sw = SWZ(so + i*16);
            CPA16(bbase + sw,         sa + i);
            CPA16(bbase + 16384 + sw, sbp + i);
        }
        CPA_COMMIT();
    };

    copy_chunk(0, 0);
    copy_chunk(1, 1);

    for (int c = 0; c < 32; c++) {
        CPA_WAIT1();               // chunk c arrived (c+1 may be in flight)
        __syncthreads();           // all warps done with chunk c-1's buffer
        if (c + 2 < 32) copy_chunk(c + 2, (c + 2) % 3);

        uint32_t bbase = sb + (c % 3)*32768;
        #pragma unroll
        for (int ks = 0; ks < 2; ks++) {
            uint32_t a_h[2][4], a_l[2][4];
            #pragma unroll
            for (int mi = 0; mi < 2; mi++) {
                int r  = m0 + mi*16 + (lane & 15);
                uint32_t kb = (uint32_t)(ks*32 + 16*(lane >> 4));   // byte offset in hi half
                LDSM4(a_h[mi], bbase + SWZ((uint32_t)(r*128) + kb));
                LDSM4(a_l[mi], bbase + SWZ((uint32_t)(r*128) + 64 + kb));
            }
            #pragma unroll
            for (int nj = 0; nj < 4; nj++) {
                int rn = n0 + nj*16 + (lane & 7) + ((lane >> 4) & 1)*8;
                uint32_t kb = (uint32_t)(ks*32 + ((lane >> 3) & 1)*16);
                uint32_t b_h[4], b_l[4];
                LDSM4(b_h, bbase + 16384 + SWZ((uint32_t)(rn*128) + kb));
                LDSM4(b_l, bbase + 16384 + SWZ((uint32_t)(rn*128) + 64 + kb));
                #pragma unroll
                for (int mi = 0; mi < 2; mi++) {
                    #pragma unroll
                    for (int t = 0; t < 2; t++) {
                        float* d = acc[mi][nj*2 + t];
                        MMA16816(d, a_h[mi], b_h + t*2);
                        MMA16816(d, a_h[mi], b_l + t*2);
                        MMA16816(d, a_l[mi], b_h + t*2);
                    }
                }
            }
        }
    }

    // Epilogue: registers -> gmem with bias (validated round-10 layout)
    #pragma unroll
    for (int mi = 0; mi < 2; mi++) {
        int r0 = bm + m0 + mi*16 + (lane >> 2);
        #pragma unroll
        for (int nt = 0; nt < 8; nt++) {
            int col = bn + n0 + nt*8 + (lane & 3)*2;
            float2 bv = *(const float2*)(bias + col);
            float2 v0, v1;
            v0.x = acc[mi][nt][0] + bv.x; v0.y = acc[mi][nt][1] + bv.y;
            v1.x = acc[mi][nt][2] + bv.x; v1.y = acc[mi][nt][3] + bv.y;
            *(float2*)(C + (size_t)r0*ldc + col)     = v0;
            *(float2*)(C + (size_t)(r0+8)*ldc + col) = v1;
        }
    }
}

// ---------------------------------------------------------------------------
// RoPE + split-bf16 conversion: g_qkv fp32 -> Q(,*0.125)/K/V split [B,H,Ts,64]
// ---------------------------------------------------------------------------
__global__ __launch_bounds__(256) void rope_split()
{
    int idx = blockIdx.x * 256 + threadIdx.x;   // BH*TS*32
    int i  = idx & 31;
    int h  = (idx >> 5) & 15;
    int ts = (idx >> 9) & 1023;
    int b  = idx >> 19;
    float freq = expf(-(float)(2*i) * (9.210340371976184f / 64.0f));
    float ang = (float)ts * freq;
    float sn, cs;
    sincosf(ang, &sn, &cs);
    size_t src = ((size_t)(b*TS + ts))*3*DD + h*HD;
    float q0 = g_qkv[src+i],      q1 = g_qkv[src+i+32];
    float k0 = g_qkv[src+DD+i],   k1 = g_qkv[src+DD+i+32];
    float v0 = g_qkv[src+2*DD+i], v1 = g_qkv[src+2*DD+i+32];
    float qr0 = (q0*cs - q1*sn) * 0.125f;
    float qr1 = (q1*cs + q0*sn) * 0.125f;
    float kr0 = k0*cs - k1*sn;
    float kr1 = k1*cs + k0*sn;
    size_t dst = ((size_t)((b*HH + h)*TS + ts))*HD;
    __nv_bfloat16 t;
    t = __float2bfloat16(qr0); g_qh[dst+i]    = t; g_ql[dst+i]    = __float2bfloat16(qr0 - __bfloat162float(t));
    t = __float2bfloat16(qr1); g_qh[dst+i+32] = t; g_ql[dst+i+32] = __float2bfloat16(qr1 - __bfloat162float(t));
    t = __float2bfloat16(kr0); g_kh[dst+i]    = t; g_kl[dst+i]    = __float2bfloat16(kr0 - __bfloat162float(t));
    t = __float2bfloat16(kr1); g_kh[dst+i+32] = t; g_kl[dst+i+32] = __float2bfloat16(kr1 - __bfloat162float(t));
    t = __float2bfloat16(v0);  g_vh[dst+i]    = t; g_vl[dst+i]    = __float2bfloat16(v0 - __bfloat162float(t));
    t = __float2bfloat16(v1);  g_vh[dst+i+32] = t; g_vl[dst+i+32] = __float2bfloat16(v1 - __bfloat162float(t));
}

// ---------------------------------------------------------------------------
// Causal flash attention on mma.sync (validated round 11).
// ---------------------------------------------------------------------------
__global__ __launch_bounds__(128, 1) void attn_mma()
{
    extern __shared__ char dsm[];
    uint32_t sb = (smem_u32(dsm) + 1023) & ~1023u;
    int tid = threadIdx.x, lane = tid & 31, wid = tid >> 5;
    int qblk = 15 - blockIdx.x;
    int bh   = blockIdx.y;
    size_t head = (size_t)bh*TS*HD;

    const uint32_t QH = sb + 65536, QL = QH + 8192;
    int crow = tid >> 1, chalf = tid & 1;
    uint32_t cso = (uint32_t)(crow*128 + chalf*64);

    auto load_tile = [&](int kt, int s) {
        uint32_t bb = sb + s*32768;
        size_t src = head + (size_t)(kt*64 + crow)*HD + chalf*32;
        const uint4* pk_h = (const uint4*)(g_kh + src);
        const uint4* pk_l = (const uint4*)(g_kl + src);
        const uint4* pv_h = (const uint4*)(g_vh + src);
        const uint4* pv_l = (const uint4*)(g_vl + src);
        #pragma unroll
        for (int i = 0; i < 4; i++) {
            uint32_t sw = SWZ(cso + i*16);
            CPA16(bb + sw,         pk_h + i);
            CPA16(bb +  8192 + sw, pk_l + i);
            CPA16(bb + 16384 + sw, pv_h + i);
            CPA16(bb + 24576 + sw, pv_l + i);
        }
        CPA_COMMIT();
    };
    load_tile(0, 0);

    {
        size_t qsrc = head + (size_t)(qblk*64 + crow)*HD + chalf*32;
        #pragma unroll
        for (int i = 0; i < 4; i++) {
            uint32_t sw = SWZ(cso + i*16);
            *(uint4*)(dsm + (QH - smem_u32(dsm)) + sw) = *(const uint4*)(g_qh + qsrc + i*8);
            *(uint4*)(dsm + (QL - smem_u32(dsm)) + sw) = *(const uint4*)(g_ql + qsrc + i*8);
        }
    }

    float o[8][4];
    #pragma unroll
    for (int j = 0; j < 8; j++)
        #pragma unroll
        for (int k = 0; k < 4; k++) o[j][k] = 0.f;
    float m0 = -1e30f, m1 = -1e30f, l0 = 0.f, l1 = 0.f;
    int r = lane >> 2, c = lane & 3;

    for (int kt = 0; kt <= qblk; kt++) {
        CPA_WAIT0();
        __syncthreads();
        if (kt < qblk) load_tile(kt + 1, (kt + 1) & 1);
        uint32_t bb = sb + (kt & 1)*32768;

        float s[8][4];
        #pragma unroll
        for (int j = 0; j < 8; j++)
            #pragma unroll
            for (int k = 0; k < 4; k++) s[j][k] = 0.f;

        #pragma unroll
        for (int ks = 0; ks < 4; ks++) {
            uint32_t aq = SWZ((uint32_t)((wid*16 + (lane & 15))*128 + (ks*16 + 8*(lane >> 4))*2));
            uint32_t a_h[4], a_l[4];
            LDSM4(a_h, QH + aq);
            LDSM4(a_l, QL + aq);
            #pragma unroll
            for (int nj = 0; nj < 4; nj++) {
                uint32_t bad = SWZ((uint32_t)((nj*16 + (lane & 7) + ((lane >> 4) & 1)*8)*128
                                              + (ks*16 + ((lane >> 3) & 1)*8)*2));
                uint32_t b_h[4], b_l[4];
                LDSM4(b_h, bb + bad);
                LDSM4(b_l, bb + 8192 + bad);
                #pragma unroll
                for (int t = 0; t < 2; t++) {
                    float* d = s[nj*2 + t];
                    MMA16816(d, a_h, b_h + t*2);
                    MMA16816(d, a_h, b_l + t*2);
                    MMA16816(d, a_l, b_h + t*2);
                }
            }
        }

        if (kt == qblk) {
            int row0 = wid*16 + r, row1 = row0 + 8;
            #pragma unroll
            for (int j = 0; j < 8; j++) {
                int col = j*8 + 2*c;
                if (col     > row0) s[j][0] = -1e30f;
                if (col + 1 > row0) s[j][1] = -1e30f;
                if (col     > row1) s[j][2] = -1e30f;
                if (col + 1 > row1) s[j][3] = -1e30f;
            }
        }

        float mx0 = -1e30f, mx1 = -1e30f;
        #pragma unroll
        for (int j = 0; j < 8; j++) {
            mx0 = fmaxf(mx0, fmaxf(s[j][0], s[j][1]));
            mx1 = fmaxf(mx1, fmaxf(s[j][2], s[j][3]));
        }
        mx0 = fmaxf(mx0, __shfl_xor_sync(0xffffffffu, mx0, 1));
        mx0 = fmaxf(mx0, __shfl_xor_sync(0xffffffffu, mx0, 2));
        mx1 = fmaxf(mx1, __shfl_xor_sync(0xffffffffu, mx1, 1));
        mx1 = fmaxf(mx1, __shfl_xor_sync(0xffffffffu, mx1, 2));
        float mn0 = fmaxf(m0, mx0), mn1 = fmaxf(m1, mx1);
        float al0 = __expf(m0 - mn0), al1 = __expf(m1 - mn1);
        m0 = mn0; m1 = mn1;
        float sum0 = 0.f, sum1 = 0.f;
        #pragma unroll
        for (int j = 0; j < 8; j++) {
            s[j][0] = __expf(s[j][0] - mn0); sum0 += s[j][0];
            s[j][1] = __expf(s[j][1] - mn0); sum0 += s[j][1];
            s[j][2] = __expf(s[j][2] - mn1); sum1 += s[j][2];
            s[j][3] = __expf(s[j][3] - mn1); sum1 += s[j][3];
        }
        sum0 += __shfl_xor_sync(0xffffffffu, sum0, 1);
        sum0 += __shfl_xor_sync(0xffffffffu, sum0, 2);
        sum1 += __shfl_xor_sync(0xffffffffu, sum1, 1);
        sum1 += __shfl_xor_sync(0xffffffffu, sum1, 2);
        l0 = l0*al0 + sum0;
        l1 = l1*al1 + sum1;
        #pragma unroll
        for (int j = 0; j < 8; j++) {
            o[j][0] *= al0; o[j][1] *= al0;
            o[j][2] *= al1; o[j][3] *= al1;
        }

        uint32_t ph[4][4], pl[4][4];
        #pragma unroll
        for (int cc = 0; cc < 4; cc++) {
            int j = 2*cc;
            pack_split(s[j][0],   s[j][1],   ph[cc][0], pl[cc][0]);
            pack_split(s[j][2],   s[j][3],   ph[cc][1], pl[cc][1]);
            pack_split(s[j+1][0], s[j+1][1], ph[cc][2], pl[cc][2]);
            pack_split(s[j+1][2], s[j+1][3], ph[cc][3], pl[cc][3]);
        }

        #pragma unroll
        for (int cc = 0; cc < 4; cc++) {
            #pragma unroll
            for (int db = 0; db < 4; db++) {
                uint32_t vad = SWZ((uint32_t)((cc*16 + (lane & 15))*128
                                              + (db*16 + 8*(lane >> 4))*2));
                uint32_t v_h[4], v_l[4];
                LDSM4T(v_h, bb + 16384 + vad);
                LDSM4T(v_l, bb + 24576 + vad);
                #pragma unroll
                for (int t = 0; t < 2; t++) {
                    float* d = o[db*2 + t];
                    MMA16816(d, ph[cc], v_h + t*2);
                    MMA16816(d, pl[cc], v_h + t*2);
                    MMA16816(d, ph[cc], v_l + t*2);
                }
            }
        }
    }

    float inv0 = 1.0f / l0, inv1 = 1.0f / l1;
    int b = bh >> 4, h = bh & 15;
    int q0g = qblk*64 + wid*16 + r;
    size_t row0 = ((size_t)(b*TS + q0g))*DD + h*HD;
    size_t row1 = row0 + (size_t)8*DD;
    #pragma unroll
    for (int j = 0; j < 8; j++) {
        int dcol = j*8 + 2*c;
        uint32_t H, L;
        pack_split(o[j][0]*inv0, o[j][1]*inv0, H, L);
        *(uint32_t*)(g_a2h + row0 + dcol) = H;
        *(uint32_t*)(g_a2l + row0 + dcol) = L;
        pack_split(o[j][2]*inv1, o[j][3]*inv1, H, L);
        *(uint32_t*)(g_a2h + row1 + dcol) = H;
        *(uint32_t*)(g_a2l + row1 + dcol) = L;
    }
}

// ---------------------------------------------------------------------------
// Linear upsample Ts->T (scale 0.25) + residual add.
// ---------------------------------------------------------------------------
__global__ __launch_bounds__(256) void upsample_kernel(const float* __restrict__ x,
                                                       float* __restrict__ outp)
{
    int gid = blockIdx.x * 256 + threadIdx.x;
    int d4 = gid & 255;
    int t  = (gid >> 8) & (TT - 1);
    int b  = gid >> 20;
    float src = ((float)t + 0.5f) * ((float)TS / (float)TT) - 0.5f;
    src = fminf(fmaxf(src, 0.0f), (float)(TS - 1));
    float fi0 = floorf(src);
    int i0 = (int)fi0;
    int i1 = min(i0 + 1, TS - 1);
    float w  = src - fi0;
    float w0 = 1.0f - w;
    const float4* pr = (const float4*)g_proj;
    float4 p0 = pr[(b*TS + i0)*256 + d4];
    float4 p1 = pr[(b*TS + i1)*256 + d4];
    float4 xv = ((const float4*)x)[gid];
    float4 ov;
    ov.x = xv.x + p0.x*w0 + p1.x*w;
    ov.y = xv.y + p0.y*w0 + p1.y*w;
    ov.z = xv.z + p0.z*w0 + p1.z*w;
    ov.w = xv.w + p0.w*w0 + p1.w*w;
    ((float4*)outp)[gid] = ov;
}

// ---------------------------------------------------------------------------
extern "C" void kernel_launch(void* const* d_in, const int* in_sizes, int n_in,
                              void* d_out, int out_size)
{
    const float* x      = (const float*)d_in[0];
    const float* norm_w = (const float*)d_in[1];
    const float* norm_b = (const float*)d_in[2];
    const float* W_qkv  = (const float*)d_in[3];
    const float* b_qkv  = (const float*)d_in[4];
    const float* W_out  = (const float*)d_in[5];
    const float* b_out  = (const float*)d_in[6];
    float* out = (float*)d_out;

    cudaFuncSetAttribute(gemm_mma, cudaFuncAttributeMaxDynamicSharedMemorySize, GSMEM);
    cudaFuncSetAttribute(attn_mma, cudaFuncAttributeMaxDynamicSharedMemorySize, ATT_SMEM);

    float *qkv_p, *proj_p;
    __nv_bfloat16 *a1h, *a1l, *a2h, *a2l, *wqh, *wql, *woh, *wol;
    cudaGetSymbolAddress((void**)&qkv_p,  g_qkv);
    cudaGetSymbolAddress((void**)&proj_p, g_proj);
    cudaGetSymbolAddress((void**)&a1h, g_a1h);
    cudaGetSymbolAddress((void**)&a1l, g_a1l);
    cudaGetSymbolAddress((void**)&a2h, g_a2h);
    cudaGetSymbolAddress((void**)&a2l, g_a2l);
    cudaGetSymbolAddress((void**)&wqh, g_wqh);
    cudaGetSymbolAddress((void**)&wql, g_wql);
    cudaGetSymbolAddress((void**)&woh, g_woh);
    cudaGetSymbolAddress((void**)&wol, g_wol);

    ln_kernel<<<MROWS, 256>>>(x, norm_w, norm_b);
    wsplit<<<dim3(3*DD/32, DD/32), 256>>>(W_qkv, wqh, wql, 3*DD);
    wsplit<<<dim3(DD/32, DD/32), 256>>>(W_out, woh, wol, DD);

    gemm_mma<<<dim3(3*DD/128, MROWS/128), 256, GSMEM>>>(a1h, a1l, wqh, wql,
                                                        b_qkv, qkv_p, 3*DD);
    rope_split<<<(BH*TS*32)/256, 256>>>();
    attn_mma<<<dim3(16, BH), 128, ATT_SMEM>>>();
    gemm_mma<<<dim3(DD/128, MROWS/128), 256, GSMEM>>>(a2h, a2l, woh, wol,
                                                      b_out, proj_p, DD);
    upsample_kernel<<<(BB*TT*DD/4)/256, 256>>>(x, out);
}

// round 17
// speedup vs baseline: 1.2802x; 1.2802x over previous
#include <cuda_runtime.h>
#include <cuda_bf16.h>
#include <math.h>
#include <stdint.h>

// Problem constants
#define BB 4
#define TT 4096
#define DD 1024
#define HH 16
#define HD 64
#define TS 1024
#define MROWS (BB*TS)
#define BH (BB*HH)

// Scratch (allocation-free: __device__ globals)
__device__ float g_qkv[MROWS*3*DD];                          // 48 MB qkv fp32
__device__ float g_proj[MROWS*DD];                           // 16 MB out projection
__device__ __nv_bfloat16 g_a1h[MROWS*DD], g_a1l[MROWS*DD];   // LN rows, split bf16
__device__ __nv_bfloat16 g_a2h[MROWS*DD], g_a2l[MROWS*DD];   // attn out, split bf16
__device__ __nv_bfloat16 g_wqh[3*DD*DD], g_wql[3*DD*DD];     // W_qkv^T split
__device__ __nv_bfloat16 g_woh[DD*DD],  g_wol[DD*DD];        // W_out^T split
// RoPE'd split-bf16 attention operands, [B,H,Ts,64]
__device__ __nv_bfloat16 g_qh[BH*TS*HD], g_ql[BH*TS*HD];
__device__ __nv_bfloat16 g_kh[BH*TS*HD], g_kl[BH*TS*HD];
__device__ __nv_bfloat16 g_vh[BH*TS*HD], g_vl[BH*TS*HD];

__device__ __forceinline__ uint32_t smem_u32(const void* p) {
    uint32_t a;
    asm("{ .reg .u64 t; cvta.to.shared.u64 t, %1; cvt.u32.u64 %0, t; }"
        : "=r"(a) : "l"(p));
    return a;
}
#define SWZ(x) ((x) ^ (((x) >> 3) & 0x70))

#define LDSM4(r, addr) \
    asm volatile("ldmatrix.sync.aligned.m8n8.x4.shared.b16 {%0,%1,%2,%3}, [%4];" \
        : "=r"((r)[0]), "=r"((r)[1]), "=r"((r)[2]), "=r"((r)[3]) : "r"(addr))

#define LDSM4T(r, addr) \
    asm volatile("ldmatrix.sync.aligned.m8n8.x4.trans.shared.b16 {%0,%1,%2,%3}, [%4];" \
        : "=r"((r)[0]), "=r"((r)[1]), "=r"((r)[2]), "=r"((r)[3]) : "r"(addr))

#define MMA16816(d, a, b) \
    asm volatile("mma.sync.aligned.m16n8k16.row.col.f32.bf16.bf16.f32 " \
        "{%0,%1,%2,%3},{%4,%5,%6,%7},{%8,%9},{%0,%1,%2,%3};" \
        : "+f"((d)[0]), "+f"((d)[1]), "+f"((d)[2]), "+f"((d)[3]) \
        : "r"((a)[0]), "r"((a)[1]), "r"((a)[2]), "r"((a)[3]), \
          "r"((b)[0]), "r"((b)[1]))

#define CPA16(dst, src) \
    asm volatile("cp.async.cg.shared.global [%0], [%1], 16;" :: "r"(dst), "l"(src) : "memory")
#define CPA_COMMIT() asm volatile("cp.async.commit_group;" ::: "memory")
#define CPA_WAIT0()  asm volatile("cp.async.wait_group 0;" ::: "memory")
#define CPA_WAIT1()  asm volatile("cp.async.wait_group 1;" ::: "memory")

#define GSMEM 197632     // gemm: 3 x 64KB stages + align slack
#define ATT_SMEM 82944   // attn: 2 x 32KB (K/V hi/lo) + 16KB Q + slack

__device__ __forceinline__ void pack_split(float a, float b, uint32_t& hi, uint32_t& lo) {
    __nv_bfloat162 h = __floats2bfloat162_rn(a, b);
    float ra = a - __bfloat162float(h.x);
    float rb = b - __bfloat162float(h.y);
    __nv_bfloat162 l2 = __floats2bfloat162_rn(ra, rb);
    hi = *(uint32_t*)&h;
    lo = *(uint32_t*)&l2;
}

// ---------------------------------------------------------------------------
// LayerNorm on strided rows -> split-bf16 A1 (hi/lo)
// ---------------------------------------------------------------------------
__global__ __launch_bounds__(256) void ln_kernel(const float* __restrict__ x,
                                                 const float* __restrict__ w,
                                                 const float* __restrict__ bias)
{
    int row = blockIdx.x;
    int b = row >> 10, ts = row & 1023;
    int tid = threadIdx.x;
    const float4* xr = (const float4*)(x + ((size_t)(b*TT + ts*4))*DD);
    float4 v = xr[tid];
    float s  = v.x + v.y + v.z + v.w;
    float sq = v.x*v.x + v.y*v.y + v.z*v.z + v.w*v.w;
    #pragma unroll
    for (int o = 16; o > 0; o >>= 1) {
        s  += __shfl_xor_sync(0xffffffffu, s,  o);
        sq += __shfl_xor_sync(0xffffffffu, sq, o);
    }
    __shared__ float rs[8], rq[8];
    int wid = tid >> 5, lane = tid & 31;
    if (lane == 0) { rs[wid] = s; rq[wid] = sq; }
    __syncthreads();
    if (tid == 0) {
        float S = 0.f, Q = 0.f;
        #pragma unroll
        for (int i = 0; i < 8; i++) { S += rs[i]; Q += rq[i]; }
        rs[0] = S; rq[0] = Q;
    }
    __syncthreads();
    float mean = rs[0] * (1.0f/DD);
    float var  = rq[0] * (1.0f/DD) - mean*mean;
    float rstd = rsqrtf(var + 1e-5f);
    float4 wv = ((const float4*)w)[tid];
    float4 bv = ((const float4*)bias)[tid];
    float vals[4];
    vals[0] = (v.x - mean)*rstd*wv.x + bv.x;
    vals[1] = (v.y - mean)*rstd*wv.y + bv.y;
    vals[2] = (v.z - mean)*rstd*wv.z + bv.z;
    vals[3] = (v.w - mean)*rstd*wv.w + bv.w;
    size_t base = (size_t)row*DD + tid*4;
    #pragma unroll
    for (int j = 0; j < 4; j += 2) {
        uint32_t H, L;
        pack_split(vals[j], vals[j+1], H, L);
        *(uint32_t*)(g_a1h + base + j) = H;
        *(uint32_t*)(g_a1l + base + j) = L;
    }
}

// ---------------------------------------------------------------------------
// Weight transpose + split: W[K=1024][N] fp32 -> T[N][1024] bf16 hi/lo
// ---------------------------------------------------------------------------
__global__ __launch_bounds__(256) void wsplit(const float* __restrict__ W,
                                              __nv_bfloat16* __restrict__ Th,
                                              __nv_bfloat16* __restrict__ Tl,
                                              int N)
{
    __shared__ float t[32][33];
    int n0 = blockIdx.x*32, k0 = blockIdx.y*32;
    int tx = threadIdx.x & 31, ty = threadIdx.x >> 5;
    #pragma unroll
    for (int i = 0; i < 4; i++)
        t[ty + i*8][tx] = W[(size_t)(k0 + ty + i*8)*N + n0 + tx];
    __syncthreads();
    #pragma unroll
    for (int i = 0; i < 4; i++) {
        int n = n0 + ty + i*8, k = k0 + tx;
        float v = t[tx][ty + i*8];
        __nv_bfloat16 h = __float2bfloat16(v);
        __nv_bfloat16 l = __float2bfloat16(v - __bfloat162float(h));
        Th[(size_t)n*DD + k] = h;
        Tl[(size_t)n*DD + k] = l;
    }
}

// ---------------------------------------------------------------------------
// mma.sync split-bf16 GEMM v2 (validated round 14) + term-major MMA order.
// Tile 128x128, 16 warps (4m x 4n, 32x32 each), K-chunk 64,
// 3-stage cp.async pipeline with wait_group 1.
// ---------------------------------------------------------------------------
__global__ __launch_bounds__(512, 1)
void gemm_mma(const __nv_bfloat16* __restrict__ Ah, const __nv_bfloat16* __restrict__ Al,
              const __nv_bfloat16* __restrict__ Bh, const __nv_bfloat16* __restrict__ Bl,
              const float* __restrict__ bias, float* __restrict__ C, int ldc)
{
    extern __shared__ char dsm[];
    uint32_t sb = (smem_u32(dsm) + 1023) & ~1023u;
    int tid = threadIdx.x, lane = tid & 31, wid = tid >> 5;
    int bn = blockIdx.x*128, bm = blockIdx.y*128;
    int m0 = (wid & 3)*32, n0 = (wid >> 2)*32;

    // gmem->smem copy mapping: row = tid/4, 32B quarter-row per array
    int row = tid >> 2, q = tid & 3;
    const uint4* gsrc[4] = {
        (const uint4*)(Ah + (size_t)(bm+row)*DD) + q*2,
        (const uint4*)(Al + (size_t)(bm+row)*DD) + q*2,
        (const uint4*)(Bh + (size_t)(bn+row)*DD) + q*2,
        (const uint4*)(Bl + (size_t)(bn+row)*DD) + q*2 };
    uint32_t so = (uint32_t)(row*128 + q*32);

    float acc[2][4][4];
    #pragma unroll
    for (int i = 0; i < 2; i++)
        #pragma unroll
        for (int j = 0; j < 4; j++)
            #pragma unroll
            for (int k = 0; k < 4; k++) acc[i][j][k] = 0.f;

    auto copy_chunk = [&](int c, int buf) {
        uint32_t bbase = sb + buf*65536;
        #pragma unroll
        for (int a = 0; a < 4; a++) {
            const uint4* src = gsrc[a] + c*8;
            uint32_t dst = bbase + a*16384;
            CPA16(dst + SWZ(so),      src);
            CPA16(dst + SWZ(so + 16), src + 1);
        }
        CPA_COMMIT();
    };

    copy_chunk(0, 0);
    copy_chunk(1, 1);

    for (int c = 0; c < 16; c++) {
        CPA_WAIT1();               // chunk c arrived (c+1 may be in flight)
        __syncthreads();           // all warps done computing chunk c-1
        if (c + 2 < 16) copy_chunk(c + 2, (c + 2) % 3);

        uint32_t bbase = sb + (c % 3)*65536;
        #pragma unroll
        for (int ks = 0; ks < 4; ks++) {
            uint32_t a_h[2][4], a_l[2][4];
            #pragma unroll
            for (int mi = 0; mi < 2; mi++) {
                int r  = m0 + mi*16 + (lane & 15);
                int kb = ks*16 + (lane >> 4)*8;
                uint32_t ad = SWZ((uint32_t)(r*128 + kb*2));
                LDSM4(a_h[mi], bbase + ad);
                LDSM4(a_l[mi], bbase + 16384 + ad);
            }
            #pragma unroll
            for (int nj = 0; nj < 2; nj++) {
                int rn = n0 + nj*16 + (lane & 7) + ((lane >> 4) & 1)*8;
                int kb = ks*16 + ((lane >> 3) & 1)*8;
                uint32_t ad = SWZ((uint32_t)(rn*128 + kb*2));
                uint32_t b_h[4], b_l[4];
                LDSM4(b_h, bbase + 32768 + ad);
                LDSM4(b_l, bbase + 49152 + ad);
                // Term-major order: consecutive MMAs hit distinct accumulators
                // (breaks the per-accumulator RAW chain). Per-accumulator
                // summation order unchanged: hh, then hl, then lh -> bit-exact.
                #pragma unroll
                for (int term = 0; term < 3; term++) {
                    #pragma unroll
                    for (int mi = 0; mi < 2; mi++) {
                        #pragma unroll
                        for (int t = 0; t < 2; t++) {
                            float* d = acc[mi][nj*2 + t];
                            const uint32_t* aa = (term == 2) ? a_l[mi] : a_h[mi];
                            const uint32_t* bb = (term == 1) ? (b_l + t*2) : (b_h + t*2);
                            MMA16816(d, aa, bb);
                        }
                    }
                }
            }
        }
    }

    // Epilogue: registers -> gmem with bias
    #pragma unroll
    for (int mi = 0; mi < 2; mi++) {
        int r0 = bm + m0 + mi*16 + (lane >> 2);
        #pragma unroll
        for (int nt = 0; nt < 4; nt++) {
            int col = bn + n0 + nt*8 + (lane & 3)*2;
            float2 bv = *(const float2*)(bias + col);
            float2 v0, v1;
            v0.x = acc[mi][nt][0] + bv.x; v0.y = acc[mi][nt][1] + bv.y;
            v1.x = acc[mi][nt][2] + bv.x; v1.y = acc[mi][nt][3] + bv.y;
            *(float2*)(C + (size_t)r0*ldc + col)     = v0;
            *(float2*)(C + (size_t)(r0+8)*ldc + col) = v1;
        }
    }
}

// ---------------------------------------------------------------------------
// RoPE + split-bf16 conversion: g_qkv fp32 -> Q(,*0.125)/K/V split [B,H,Ts,64]
// ---------------------------------------------------------------------------
__global__ __launch_bounds__(256) void rope_split()
{
    int idx = blockIdx.x * 256 + threadIdx.x;   // BH*TS*32
    int i  = idx & 31;
    int h  = (idx >> 5) & 15;
    int ts = (idx >> 9) & 1023;
    int b  = idx >> 19;
    float freq = expf(-(float)(2*i) * (9.210340371976184f / 64.0f));
    float ang = (float)ts * freq;
    float sn, cs;
    sincosf(ang, &sn, &cs);
    size_t src = ((size_t)(b*TS + ts))*3*DD + h*HD;
    float q0 = g_qkv[src+i],      q1 = g_qkv[src+i+32];
    float k0 = g_qkv[src+DD+i],   k1 = g_qkv[src+DD+i+32];
    float v0 = g_qkv[src+2*DD+i], v1 = g_qkv[src+2*DD+i+32];
    float qr0 = (q0*cs - q1*sn) * 0.125f;
    float qr1 = (q1*cs + q0*sn) * 0.125f;
    float kr0 = k0*cs - k1*sn;
    float kr1 = k1*cs + k0*sn;
    size_t dst = ((size_t)((b*HH + h)*TS + ts))*HD;
    __nv_bfloat16 t;
    t = __float2bfloat16(qr0); g_qh[dst+i]    = t; g_ql[dst+i]    = __float2bfloat16(qr0 - __bfloat162float(t));
    t = __float2bfloat16(qr1); g_qh[dst+i+32] = t; g_ql[dst+i+32] = __float2bfloat16(qr1 - __bfloat162float(t));
    t = __float2bfloat16(kr0); g_kh[dst+i]    = t; g_kl[dst+i]    = __float2bfloat16(kr0 - __bfloat162float(t));
    t = __float2bfloat16(kr1); g_kh[dst+i+32] = t; g_kl[dst+i+32] = __float2bfloat16(kr1 - __bfloat162float(t));
    t = __float2bfloat16(v0);  g_vh[dst+i]    = t; g_vl[dst+i]    = __float2bfloat16(v0 - __bfloat162float(t));
    t = __float2bfloat16(v1);  g_vh[dst+i+32] = t; g_vl[dst+i+32] = __float2bfloat16(v1 - __bfloat162float(t));
}

// ---------------------------------------------------------------------------
// Causal flash attention on mma.sync (validated round 11).
// ---------------------------------------------------------------------------
__global__ __launch_bounds__(128, 1) void attn_mma()
{
    extern __shared__ char dsm[];
    uint32_t sb = (smem_u32(dsm) + 1023) & ~1023u;
    int tid = threadIdx.x, lane = tid & 31, wid = tid >> 5;
    int qblk = 15 - blockIdx.x;
    int bh   = blockIdx.y;
    size_t head = (size_t)bh*TS*HD;

    const uint32_t QH = sb + 65536, QL = QH + 8192;
    int crow = tid >> 1, chalf = tid & 1;
    uint32_t cso = (uint32_t)(crow*128 + chalf*64);

    auto load_tile = [&](int kt, int s) {
        uint32_t bb = sb + s*32768;
        size_t src = head + (size_t)(kt*64 + crow)*HD + chalf*32;
        const uint4* pk_h = (const uint4*)(g_kh + src);
        const uint4* pk_l = (const uint4*)(g_kl + src);
        const uint4* pv_h = (const uint4*)(g_vh + src);
        const uint4* pv_l = (const uint4*)(g_vl + src);
        #pragma unroll
        for (int i = 0; i < 4; i++) {
            uint32_t sw = SWZ(cso + i*16);
            CPA16(bb + sw,         pk_h + i);
            CPA16(bb +  8192 + sw, pk_l + i);
            CPA16(bb + 16384 + sw, pv_h + i);
            CPA16(bb + 24576 + sw, pv_l + i);
        }
        CPA_COMMIT();
    };
    load_tile(0, 0);

    {
        size_t qsrc = head + (size_t)(qblk*64 + crow)*HD + chalf*32;
        #pragma unroll
        for (int i = 0; i < 4; i++) {
            uint32_t sw = SWZ(cso + i*16);
            *(uint4*)(dsm + (QH - smem_u32(dsm)) + sw) = *(const uint4*)(g_qh + qsrc + i*8);
            *(uint4*)(dsm + (QL - smem_u32(dsm)) + sw) = *(const uint4*)(g_ql + qsrc + i*8);
        }
    }

    float o[8][4];
    #pragma unroll
    for (int j = 0; j < 8; j++)
        #pragma unroll
        for (int k = 0; k < 4; k++) o[j][k] = 0.f;
    float m0 = -1e30f, m1 = -1e30f, l0 = 0.f, l1 = 0.f;
    int r = lane >> 2, c = lane & 3;

    for (int kt = 0; kt <= qblk; kt++) {
        CPA_WAIT0();
        __syncthreads();
        if (kt < qblk) load_tile(kt + 1, (kt + 1) & 1);
        uint32_t bb = sb + (kt & 1)*32768;

        float s[8][4];
        #pragma unroll
        for (int j = 0; j < 8; j++)
            #pragma unroll
            for (int k = 0; k < 4; k++) s[j][k] = 0.f;

        #pragma unroll
        for (int ks = 0; ks < 4; ks++) {
            uint32_t aq = SWZ((uint32_t)((wid*16 + (lane & 15))*128 + (ks*16 + 8*(lane >> 4))*2));
            uint32_t a_h[4], a_l[4];
            LDSM4(a_h, QH + aq);
            LDSM4(a_l, QL + aq);
            #pragma unroll
            for (int nj = 0; nj < 4; nj++) {
                uint32_t bad = SWZ((uint32_t)((nj*16 + (lane & 7) + ((lane >> 4) & 1)*8)*128
                                              + (ks*16 + ((lane >> 3) & 1)*8)*2));
                uint32_t b_h[4], b_l[4];
                LDSM4(b_h, bb + bad);
                LDSM4(b_l, bb + 8192 + bad);
                #pragma unroll
                for (int t = 0; t < 2; t++) {
                    float* d = s[nj*2 + t];
                    MMA16816(d, a_h, b_h + t*2);
                    MMA16816(d, a_h, b_l + t*2);
                    MMA16816(d, a_l, b_h + t*2);
                }
            }
        }

        if (kt == qblk) {
            int row0 = wid*16 + r, row1 = row0 + 8;
            #pragma unroll
            for (int j = 0; j < 8; j++) {
                int col = j*8 + 2*c;
                if (col     > row0) s[j][0] = -1e30f;
                if (col + 1 > row0) s[j][1] = -1e30f;
                if (col     > row1) s[j][2] = -1e30f;
                if (col + 1 > row1) s[j][3] = -1e30f;
            }
        }

        float mx0 = -1e30f, mx1 = -1e30f;
        #pragma unroll
        for (int j = 0; j < 8; j++) {
            mx0 = fmaxf(mx0, fmaxf(s[j][0], s[j][1]));
            mx1 = fmaxf(mx1, fmaxf(s[j][2], s[j][3]));
        }
        mx0 = fmaxf(mx0, __shfl_xor_sync(0xffffffffu, mx0, 1));
        mx0 = fmaxf(mx0, __shfl_xor_sync(0xffffffffu, mx0, 2));
        mx1 = fmaxf(mx1, __shfl_xor_sync(0xffffffffu, mx1, 1));
        mx1 = fmaxf(mx1, __shfl_xor_sync(0xffffffffu, mx1, 2));
        float mn0 = fmaxf(m0, mx0), mn1 = fmaxf(m1, mx1);
        float al0 = __expf(m0 - mn0), al1 = __expf(m1 - mn1);
        m0 = mn0; m1 = mn1;
        float sum0 = 0.f, sum1 = 0.f;
        #pragma unroll
        for (int j = 0; j < 8; j++) {
            s[j][0] = __expf(s[j][0] - mn0); sum0 += s[j][0];
            s[j][1] = __expf(s[j][1] - mn0); sum0 += s[j][1];
            s[j][2] = __expf(s[j][2] - mn1); sum1 += s[j][2];
            s[j][3] = __expf(s[j][3] - mn1); sum1 += s[j][3];
        }
        sum0 += __shfl_xor_sync(0xffffffffu, sum0, 1);
        sum0 += __shfl_xor_sync(0xffffffffu, sum0, 2);
        sum1 += __shfl_xor_sync(0xffffffffu, sum1, 1);
        sum1 += __shfl_xor_sync(0xffffffffu, sum1, 2);
        l0 = l0*al0 + sum0;
        l1 = l1*al1 + sum1;
        #pragma unroll
        for (int j = 0; j < 8; j++) {
            o[j][0] *= al0; o[j][1] *= al0;
            o[j][2] *= al1; o[j][3] *= al1;
        }

        uint32_t ph[4][4], pl[4][4];
        #pragma unroll
        for (int cc = 0; cc < 4; cc++) {
            int j = 2*cc;
            pack_split(s[j][0],   s[j][1],   ph[cc][0], pl[cc][0]);
            pack_split(s[j][2],   s[j][3],   ph[cc][1], pl[cc][1]);
            pack_split(s[j+1][0], s[j+1][1], ph[cc][2], pl[cc][2]);
            pack_split(s[j+1][2], s[j+1][3], ph[cc][3], pl[cc][3]);
        }

        #pragma unroll
        for (int cc = 0; cc < 4; cc++) {
            #pragma unroll
            for (int db = 0; db < 4; db++) {
                uint32_t vad = SWZ((uint32_t)((cc*16 + (lane & 15))*128
                                              + (db*16 + 8*(lane >> 4))*2));
                uint32_t v_h[4], v_l[4];
                LDSM4T(v_h, bb + 16384 + vad);
                LDSM4T(v_l, bb + 24576 + vad);
                #pragma unroll
                for (int t = 0; t < 2; t++) {
                    float* d = o[db*2 + t];
                    MMA16816(d, ph[cc], v_h + t*2);
                    MMA16816(d, pl[cc], v_h + t*2);
                    MMA16816(d, ph[cc], v_l + t*2);
                }
            }
        }
    }

    float inv0 = 1.0f / l0, inv1 = 1.0f / l1;
    int b = bh >> 4, h = bh & 15;
    int q0g = qblk*64 + wid*16 + r;
    size_t row0 = ((size_t)(b*TS + q0g))*DD + h*HD;
    size_t row1 = row0 + (size_t)8*DD;
    #pragma unroll
    for (int j = 0; j < 8; j++) {
        int dcol = j*8 + 2*c;
        uint32_t H, L;
        pack_split(o[j][0]*inv0, o[j][1]*inv0, H, L);
        *(uint32_t*)(g_a2h + row0 + dcol) = H;
        *(uint32_t*)(g_a2l + row0 + dcol) = L;
        pack_split(o[j][2]*inv1, o[j][3]*inv1, H, L);
        *(uint32_t*)(g_a2h + row1 + dcol) = H;
        *(uint32_t*)(g_a2l + row1 + dcol) = L;
    }
}

// ---------------------------------------------------------------------------
// Linear upsample Ts->T (scale 0.25) + residual add.
// ---------------------------------------------------------------------------
__global__ __launch_bounds__(256) void upsample_kernel(const float* __restrict__ x,
                                                       float* __restrict__ outp)
{
    int gid = blockIdx.x * 256 + threadIdx.x;
    int d4 = gid & 255;
    int t  = (gid >> 8) & (TT - 1);
    int b  = gid >> 20;
    float src = ((float)t + 0.5f) * ((float)TS / (float)TT) - 0.5f;
    src = fminf(fmaxf(src, 0.0f), (float)(TS - 1));
    float fi0 = floorf(src);
    int i0 = (int)fi0;
    int i1 = min(i0 + 1, TS - 1);
    float w  = src - fi0;
    float w0 = 1.0f - w;
    const float4* pr = (const float4*)g_proj;
    float4 p0 = pr[(b*TS + i0)*256 + d4];
    float4 p1 = pr[(b*TS + i1)*256 + d4];
    float4 xv = ((const float4*)x)[gid];
    float4 ov;
    ov.x = xv.x + p0.x*w0 + p1.x*w;
    ov.y = xv.y + p0.y*w0 + p1.y*w;
    ov.z = xv.z + p0.z*w0 + p1.z*w;
    ov.w = xv.w + p0.w*w0 + p1.w*w;
    ((float4*)outp)[gid] = ov;
}

// ---------------------------------------------------------------------------
extern "C" void kernel_launch(void* const* d_in, const int* in_sizes, int n_in,
                              void* d_out, int out_size)
{
    const float* x      = (const float*)d_in[0];
    const float* norm_w = (const float*)d_in[1];
    const float* norm_b = (const float*)d_in[2];
    const float* W_qkv  = (const float*)d_in[3];
    const float* b_qkv  = (const float*)d_in[4];
    const float* W_out  = (const float*)d_in[5];
    const float* b_out  = (const float*)d_in[6];
    float* out = (float*)d_out;

    cudaFuncSetAttribute(gemm_mma, cudaFuncAttributeMaxDynamicSharedMemorySize, GSMEM);
    cudaFuncSetAttribute(attn_mma, cudaFuncAttributeMaxDynamicSharedMemorySize, ATT_SMEM);

    float *qkv_p, *proj_p;
    __nv_bfloat16 *a1h, *a1l, *a2h, *a2l, *wqh, *wql, *woh, *wol;
    cudaGetSymbolAddress((void**)&qkv_p,  g_qkv);
    cudaGetSymbolAddress((void**)&proj_p, g_proj);
    cudaGetSymbolAddress((void**)&a1h, g_a1h);
    cudaGetSymbolAddress((void**)&a1l, g_a1l);
    cudaGetSymbolAddress((void**)&a2h, g_a2h);
    cudaGetSymbolAddress((void**)&a2l, g_a2l);
    cudaGetSymbolAddress((void**)&wqh, g_wqh);
    cudaGetSymbolAddress((void**)&wql, g_wql);
    cudaGetSymbolAddress((void**)&woh, g_woh);
    cudaGetSymbolAddress((void**)&wol, g_wol);

    ln_kernel<<<MROWS, 256>>>(x, norm_w, norm_b);
    wsplit<<<dim3(3*DD/32, DD/32), 256>>>(W_qkv, wqh, wql, 3*DD);
    wsplit<<<dim3(DD/32, DD/32), 256>>>(W_out, woh, wol, DD);

    gemm_mma<<<dim3(3*DD/128, MROWS/128), 512, GSMEM>>>(a1h, a1l, wqh, wql,
                                                        b_qkv, qkv_p, 3*DD);
    rope_split<<<(BH*TS*32)/256, 256>>>();
    attn_mma<<<dim3(16, BH), 128, ATT_SMEM>>>();
    gemm_mma<<<dim3(DD/128, MROWS/128), 512, GSMEM>>>(a2h, a2l, woh, wol,
                                                      b_out, proj_p, DD);
    upsample_kernel<<<(BB*TT*DD/4)/256, 256>>>(x, out);
}